// round 1
// baseline (speedup 1.0000x reference)
#include <cuda_runtime.h>
#include <math.h>
#include <stdint.h>

// Problem constants
// B=64, T_IN=12, HORIZON=12, N=512, H=64, TD=32, ED=16, CHEB_K=3, D_HEADS=8
// M = B*HORIZON = 768, BN pairs = B*N = 32768

// ---------------- device scratch (allocation-free) ----------------
__device__ float g_A[512*512];                       // adjacency (row softmax)
__device__ float g_pq[768*64];                       // STE_Q @ Wq_top + bq
__device__ float g_pk[64*64];                        // STE_P @ Wk_top + bk
__device__ float g_pv[64*64];                        // STE_P @ Wv_top + bv
__device__ float g_qkvu[(size_t)32768*256];          // per (b,n): [qx|k|v|u]
__device__ float g_de[(size_t)768*512*64];           // de_input
__device__ float g_y1[(size_t)768*512*64];           // A @ y0
__device__ float g_y2[(size_t)768*512*64];           // 2A@y1 - y0
__device__ float g_yz[(size_t)768*512*64];           // z * de_input
__device__ float g_hc[(size_t)768*512*64];           // tanh gcn2
__device__ float g_zr[(size_t)768*512*128];          // sigmoid gcn1
__device__ float g_W1[(size_t)768*3*65*128];         // per-batch gcn1 weights
__device__ float g_b1[768*128];
__device__ float g_Wu[(size_t)768*3*65*64];          // per-batch gcn2 weights
__device__ float g_bu[768*64];

__device__ __forceinline__ float* buf_sel(int id){
  return id==0 ? g_de : id==1 ? g_y1 : id==2 ? g_y2 : g_yz;
}
__device__ __forceinline__ float* wbuf_sel(int id){
  return id==0 ? g_W1 : id==1 ? g_Wu : id==2 ? g_b1 : g_bu;
}

// ---------------- 1) adjacency: A = softmax(relu(E E^T), axis=1) ----------------
__global__ void k_adj(const float* __restrict__ E){
  int i = blockIdx.x;         // row
  int j = threadIdx.x;        // col (512 threads)
  __shared__ float Ei[16];
  __shared__ float red[512];
  if (j < 16) Ei[j] = E[i*16 + j];
  __syncthreads();
  float d = 0.f;
  #pragma unroll
  for (int c = 0; c < 16; c++) d = fmaf(Ei[c], E[j*16 + c], d);
  d = fmaxf(d, 0.f);
  red[j] = d; __syncthreads();
  for (int s = 256; s > 0; s >>= 1){ if (j < s) red[j] = fmaxf(red[j], red[j+s]); __syncthreads(); }
  float mx = red[0];
  __syncthreads();
  float e = __expf(d - mx);
  red[j] = e; __syncthreads();
  for (int s = 256; s > 0; s >>= 1){ if (j < s) red[j] += red[j+s]; __syncthreads(); }
  g_A[i*512 + j] = e * (1.f / red[0]);
}

// ---------------- 2) STE projections (tiny) ----------------
__global__ void k_prep(const float* __restrict__ ne1, const float* __restrict__ ne2,
                       const float* __restrict__ Wq, const float* __restrict__ bq,
                       const float* __restrict__ Wk, const float* __restrict__ bk,
                       const float* __restrict__ Wv, const float* __restrict__ bv){
  int row = blockIdx.x;
  int o = threadIdx.x;   // 64 threads
  if (row < 768){
    const float* e = ne2 + row*32;
    float a = bq[o];
    #pragma unroll
    for (int d = 0; d < 32; d++) a = fmaf(e[d], Wq[d*64 + o], a);
    g_pq[row*64 + o] = a;
  } else if (row < 832){
    int b = row - 768;
    const float* e = ne1 + (b*12 + 11)*32;   // STE_P = node_embedding1[:, -1, :]
    float a = bk[o];
    #pragma unroll
    for (int d = 0; d < 32; d++) a = fmaf(e[d], Wk[d*64 + o], a);
    g_pk[b*64 + o] = a;
  } else {
    int b = row - 832;
    const float* e = ne1 + (b*12 + 11)*32;
    float a = bv[o];
    #pragma unroll
    for (int d = 0; d < 32; d++) a = fmaf(e[d], Wv[d*64 + o], a);
    g_pv[b*64 + o] = a;
  }
}

// ---------------- 3) qx/k/v/u GEMM: (32768 x 64) @ (64 x 64) x4 matrices ----------------
// blockIdx.x = which matrix (0:qx 1:k 2:v 3:u), blockIdx.y = 64-row tile
__global__ void k_qkvu(const float* __restrict__ X, const float* __restrict__ Wq,
                       const float* __restrict__ Wk, const float* __restrict__ Wv,
                       const float* __restrict__ taw, const float* __restrict__ tab){
  int mode = blockIdx.x;
  int row0 = blockIdx.y * 64;
  const float* Wsrc = (mode==0) ? Wq + 2048 : (mode==1) ? Wk + 2048
                    : (mode==2) ? Wv + 2048 : taw;   // X-part rows 32..95 of W*, or ta_w[0]
  __shared__ float As[64][65];
  __shared__ float Bs[64][65];
  int tid = threadIdx.x;
  #pragma unroll
  for (int i = 0; i < 4; i++){
    int idx = tid + i*256;
    int r = idx >> 4, kq = idx & 15;
    float4 a4 = *(const float4*)(X + (size_t)(row0 + r)*64 + kq*4);
    As[r][kq*4+0]=a4.x; As[r][kq*4+1]=a4.y; As[r][kq*4+2]=a4.z; As[r][kq*4+3]=a4.w;
    float4 w4 = *(const float4*)(Wsrc + (size_t)r*64 + kq*4);
    Bs[r][kq*4+0]=w4.x; Bs[r][kq*4+1]=w4.y; Bs[r][kq*4+2]=w4.z; Bs[r][kq*4+3]=w4.w;
  }
  __syncthreads();
  int ty = tid >> 4, tx = tid & 15;
  float acc[4][4];
  #pragma unroll
  for (int i=0;i<4;i++){ acc[i][0]=0.f; acc[i][1]=0.f; acc[i][2]=0.f; acc[i][3]=0.f; }
  #pragma unroll 16
  for (int k = 0; k < 64; k++){
    float a[4], b[4];
    #pragma unroll
    for (int i=0;i<4;i++) a[i] = As[ty*4+i][k];
    #pragma unroll
    for (int j=0;j<4;j++) b[j] = Bs[k][tx*4+j];
    #pragma unroll
    for (int i=0;i<4;i++)
      #pragma unroll
      for (int j=0;j<4;j++) acc[i][j] = fmaf(a[i], b[j], acc[i][j]);
  }
  #pragma unroll
  for (int i=0;i<4;i++){
    int r = row0 + ty*4 + i;
    int bb = r >> 9;
    #pragma unroll
    for (int j=0;j<4;j++){
      int c = tx*4 + j;
      float v = acc[i][j];
      if (mode == 1)      v = fmaxf(v + g_pk[bb*64 + c], 0.f);
      else if (mode == 2) v = fmaxf(v + g_pv[bb*64 + c], 0.f);
      else if (mode == 3) v = v + tab[c];
      g_qkvu[(size_t)r*256 + mode*64 + c] = v;
    }
  }
}

// ---------------- 4) fused attention + output projection -> de_input ----------------
// warp per (b,n). de[b,t,n,:] = u + sum_d attn[d,t] * (v_head_d @ ta_w1_rows_d)
__global__ void k_attn2(const float* __restrict__ taw){
  const float* taw1 = taw + 4096;
  __shared__ float tw[64][64];
  __shared__ float qs[8][64], ks[8][64], vs[8][64];
  __shared__ float es[8][8][12];
  for (int i = threadIdx.x; i < 4096; i += 256) tw[i>>6][i&63] = taw1[i];
  __syncthreads();
  int w = threadIdx.x >> 5;
  int lane = threadIdx.x & 31;
  int bn = blockIdx.x*8 + w;
  int b = bn >> 9, n = bn & 511;
  const float* base = g_qkvu + (size_t)bn*256;
  int c0 = lane*2, c1 = c0 + 1;
  float qx0 = base[c0],     qx1 = base[c1];
  float kk0 = base[64+c0],  kk1 = base[64+c1];
  float vv0 = base[128+c0], vv1 = base[128+c1];
  float u0  = base[192+c0], u1  = base[192+c1];
  qs[w][c0]=qx0; qs[w][c1]=qx1;
  ks[w][c0]=kk0; ks[w][c1]=kk1;
  vs[w][c0]=vv0; vs[w][c1]=vv1;
  __syncwarp();
  // vw[d][c] = sum_{cp<8} v[d*8+cp] * ta_w1[d*8+cp][c]
  float vw0[8], vw1[8];
  #pragma unroll
  for (int d = 0; d < 8; d++){
    float a0 = 0.f, a1 = 0.f;
    #pragma unroll
    for (int cp = 0; cp < 8; cp++){
      float vv = vs[w][d*8+cp];
      float2 t2 = *(const float2*)&tw[d*8+cp][c0];
      a0 = fmaf(vv, t2.x, a0); a1 = fmaf(vv, t2.y, a1);
    }
    vw0[d] = a0; vw1[d] = a1;
  }
  // logits e[d][t] = sum_cp relu(qx + pq)[d*8+cp] * k[d*8+cp]
  for (int task = lane; task < 96; task += 32){
    int d = task / 12, t = task - d*12;
    const float* pq = g_pq + (size_t)(b*12 + t)*64 + d*8;
    float e = 0.f;
    #pragma unroll
    for (int cp = 0; cp < 8; cp++){
      float q = fmaxf(qs[w][d*8+cp] + pq[cp], 0.f);
      e = fmaf(q, ks[w][d*8+cp], e);
    }
    es[w][d][t] = e;
  }
  __syncwarp();
  if (lane < 8){  // softmax over t per head
    float mx = -1e30f;
    #pragma unroll
    for (int t=0;t<12;t++) mx = fmaxf(mx, es[w][lane][t]);
    float ssum = 0.f;
    #pragma unroll
    for (int t=0;t<12;t++){ float ex = __expf(es[w][lane][t]-mx); es[w][lane][t]=ex; ssum+=ex; }
    float inv = 1.f/ssum;
    #pragma unroll
    for (int t=0;t<12;t++) es[w][lane][t] *= inv;
  }
  __syncwarp();
  #pragma unroll
  for (int t = 0; t < 12; t++){
    float o0 = u0, o1 = u1;
    #pragma unroll
    for (int d = 0; d < 8; d++){
      float a = es[w][d][t];
      o0 = fmaf(a, vw0[d], o0); o1 = fmaf(a, vw1[d], o1);
    }
    size_t off = ((size_t)(b*12 + t)*512 + n)*64;
    *(float2*)(g_de + off + c0) = make_float2(o0, o1);
  }
}

// ---------------- 5) per-batch weight gen: C(768 x Nc) = ne2(768x32) @ Bw(32xNc) + g ----------------
__global__ void k_wgen(const float* __restrict__ Am, const float* __restrict__ Bw,
                       const float* __restrict__ g, int Nc, int dst){
  float* C = wbuf_sel(dst);
  int col0 = blockIdx.x * 64, row0 = blockIdx.y * 64;
  __shared__ float As[64][33];
  __shared__ float Bs[32][65];
  int tid = threadIdx.x;
  #pragma unroll
  for (int i = 0; i < 2; i++){
    int idx = tid + i*256;
    { int r = idx >> 3, kq = idx & 7;
      float4 a4 = *(const float4*)(Am + (size_t)(row0 + r)*32 + kq*4);
      As[r][kq*4+0]=a4.x; As[r][kq*4+1]=a4.y; As[r][kq*4+2]=a4.z; As[r][kq*4+3]=a4.w; }
    { int r = idx >> 4, cq = idx & 15;
      float4 b4 = *(const float4*)(Bw + (size_t)r*Nc + col0 + cq*4);
      Bs[r][cq*4+0]=b4.x; Bs[r][cq*4+1]=b4.y; Bs[r][cq*4+2]=b4.z; Bs[r][cq*4+3]=b4.w; }
  }
  __syncthreads();
  int ty = tid >> 4, tx = tid & 15;
  float acc[4][4];
  #pragma unroll
  for (int i=0;i<4;i++){ acc[i][0]=0.f; acc[i][1]=0.f; acc[i][2]=0.f; acc[i][3]=0.f; }
  #pragma unroll
  for (int k = 0; k < 32; k++){
    float a[4], b[4];
    #pragma unroll
    for (int i=0;i<4;i++) a[i] = As[ty*4+i][k];
    #pragma unroll
    for (int j=0;j<4;j++) b[j] = Bs[k][tx*4+j];
    #pragma unroll
    for (int i=0;i<4;i++)
      #pragma unroll
      for (int j=0;j<4;j++) acc[i][j] = fmaf(a[i], b[j], acc[i][j]);
  }
  #pragma unroll
  for (int i=0;i<4;i++){
    int r = row0 + ty*4 + i;
    #pragma unroll
    for (int j=0;j<4;j++){
      int c = col0 + tx*4 + j;
      C[(size_t)r*Nc + c] = acc[i][j] + g[c];
    }
  }
}

// ---------------- 6) batched adjacency GEMM: Out[b] = A @ X[b] (opt: 2*... - Z[b]) ----------------
// 128 threads, BM=128, BN=64 (full), BK=16, 8x8 microtile
__global__ void k_agemm(int src_id, int dst_id, int sub_id){
  const float* __restrict__ Xin = buf_sel(src_id);
  float* __restrict__ Out = buf_sel(dst_id);
  const float* Zs = (sub_id >= 0) ? buf_sel(sub_id) : nullptr;
  int bt = blockIdx.y;
  int row0 = blockIdx.x * 128;
  const float* Xb = Xin + (size_t)bt*512*64;
  __shared__ float As[128][17];
  __shared__ __align__(16) float Bs[16][64];
  int tid = threadIdx.x;
  int tx = tid & 7, ty = tid >> 3;
  float acc[8][8];
  #pragma unroll
  for (int i=0;i<8;i++)
    #pragma unroll
    for (int j=0;j<8;j++) acc[i][j] = 0.f;
  for (int k0 = 0; k0 < 512; k0 += 16){
    #pragma unroll
    for (int i = 0; i < 4; i++){
      int idx = tid + i*128;
      int r = idx >> 2, kq = idx & 3;
      float4 a4 = *(const float4*)(g_A + (size_t)(row0 + r)*512 + k0 + kq*4);
      As[r][kq*4+0]=a4.x; As[r][kq*4+1]=a4.y; As[r][kq*4+2]=a4.z; As[r][kq*4+3]=a4.w;
    }
    #pragma unroll
    for (int i = 0; i < 2; i++){
      int idx = tid + i*128;
      int r = idx >> 4, cq = idx & 15;
      float4 b4 = *(const float4*)(Xb + (size_t)(k0 + r)*64 + cq*4);
      *(float4*)&Bs[r][cq*4] = b4;
    }
    __syncthreads();
    #pragma unroll
    for (int k = 0; k < 16; k++){
      float a[8], b[8];
      #pragma unroll
      for (int i=0;i<8;i++) a[i] = As[ty*8+i][k];
      float4 b0 = *(const float4*)&Bs[k][tx*8];
      float4 b1 = *(const float4*)&Bs[k][tx*8+4];
      b[0]=b0.x; b[1]=b0.y; b[2]=b0.z; b[3]=b0.w;
      b[4]=b1.x; b[5]=b1.y; b[6]=b1.z; b[7]=b1.w;
      #pragma unroll
      for (int i=0;i<8;i++)
        #pragma unroll
        for (int j=0;j<8;j++) acc[i][j] = fmaf(a[i], b[j], acc[i][j]);
    }
    __syncthreads();
  }
  float* Ob = Out + (size_t)bt*512*64;
  const float* Zb = Zs ? Zs + (size_t)bt*512*64 : nullptr;
  #pragma unroll
  for (int i=0;i<8;i++){
    size_t r = row0 + ty*8 + i;
    #pragma unroll
    for (int j=0;j<8;j++){
      float v = acc[i][j];
      if (Zb) v = 2.f*v - Zb[r*64 + tx*8 + j];
      Ob[r*64 + tx*8 + j] = v;
    }
  }
}

// ---------------- 7) combine GEMM: act( [Y0|Y1|Y2](512x192) @ Wsel[b](192xNo) + bias[b] ) ----------------
template<int WHICH>   // 0: gcn1 -> sigmoid, zr (No=128) ; 1: gcn2 -> tanh, hc (No=64)
__global__ void k_comb(){
  constexpr int No = WHICH ? 64 : 128;
  const float* Y0   = WHICH ? g_yz : g_de;
  const float* W    = WHICH ? g_Wu : g_W1;
  const float* bias = WHICH ? g_bu : g_b1;
  float* Out        = WHICH ? g_hc : g_zr;
  int bt = blockIdx.z;
  int row0 = blockIdx.y * 64, col0 = blockIdx.x * 64;
  __shared__ float As[64][33];
  __shared__ float Bs[32][65];
  int tid = threadIdx.x, ty = tid >> 4, tx = tid & 15;
  float acc[4][4];
  #pragma unroll
  for (int i=0;i<4;i++){ acc[i][0]=0.f; acc[i][1]=0.f; acc[i][2]=0.f; acc[i][3]=0.f; }
  for (int k0 = 0; k0 < 192; k0 += 32){
    int seg = k0 >> 6, kin0 = k0 & 63;
    const float* Yb = (seg==0 ? Y0 : seg==1 ? g_y1 : g_y2) + (size_t)bt*512*64;
    #pragma unroll
    for (int i = 0; i < 2; i++){
      int idx = tid + i*256;
      int r = idx >> 3, kq = idx & 7;
      float4 a4 = *(const float4*)(Yb + (size_t)(row0 + r)*64 + kin0 + kq*4);
      As[r][kq*4+0]=a4.x; As[r][kq*4+1]=a4.y; As[r][kq*4+2]=a4.z; As[r][kq*4+3]=a4.w;
    }
    // weight rows i = kin0+r+1 (channel 0 of gcn input is identically zero)
    const float* Wb = W + ((size_t)bt*3 + seg)*65*No + (size_t)(kin0 + 1)*No + col0;
    #pragma unroll
    for (int i = 0; i < 2; i++){
      int idx = tid + i*256;
      int r = idx >> 4, cq = idx & 15;
      float4 w4 = *(const float4*)(Wb + (size_t)r*No + cq*4);
      Bs[r][cq*4+0]=w4.x; Bs[r][cq*4+1]=w4.y; Bs[r][cq*4+2]=w4.z; Bs[r][cq*4+3]=w4.w;
    }
    __syncthreads();
    #pragma unroll
    for (int k = 0; k < 32; k++){
      float a[4], b[4];
      #pragma unroll
      for (int i=0;i<4;i++) a[i] = As[ty*4+i][k];
      #pragma unroll
      for (int j=0;j<4;j++) b[j] = Bs[k][tx*4+j];
      #pragma unroll
      for (int i=0;i<4;i++)
        #pragma unroll
        for (int j=0;j<4;j++) acc[i][j] = fmaf(a[i], b[j], acc[i][j]);
    }
    __syncthreads();
  }
  float* Ob = Out + ((size_t)bt*512 + row0)*No + col0;
  #pragma unroll
  for (int i=0;i<4;i++){
    #pragma unroll
    for (int j=0;j<4;j++){
      float v = acc[i][j] + bias[bt*No + col0 + tx*4 + j];
      v = WHICH ? tanhf(v) : 1.f/(1.f + __expf(-v));
      Ob[(size_t)(ty*4+i)*No + tx*4 + j] = v;
    }
  }
}

// ---------------- 8) yz = z * de ----------------
__global__ void k_zde(){
  size_t idx = (size_t)blockIdx.x * blockDim.x + threadIdx.x;
  if (idx >= (size_t)768*512*64) return;
  size_t mn = idx >> 6;
  int h = (int)(idx & 63);
  g_yz[idx] = g_zr[(mn << 7) + h] * g_de[idx];
}

// ---------------- 9) final: out[m,n] = sum_h (rg*de + (1-rg)*hc) * out_w[t,h] + out_b[t] ----------------
__global__ void k_out(const float* __restrict__ outw, const float* __restrict__ outb,
                      float* __restrict__ out){
  int gw = blockIdx.x*8 + (threadIdx.x >> 5);
  int lane = threadIdx.x & 31;
  size_t mn = (size_t)gw;
  int m = gw >> 9;
  int t = m % 12;
  size_t base = mn << 6;
  float s = 0.f;
  #pragma unroll
  for (int ii = 0; ii < 2; ii++){
    int i = lane + ii*32;
    float rg = g_zr[(mn << 7) + 64 + i];
    float de = g_de[base + i];
    float hc = g_hc[base + i];
    float st = fmaf(rg, de - hc, hc);     // rg*de + (1-rg)*hc
    s = fmaf(st, outw[t*64 + i], s);
  }
  #pragma unroll
  for (int off = 16; off > 0; off >>= 1) s += __shfl_xor_sync(0xffffffffu, s, off);
  if (lane == 0) out[mn] = s + outb[t];
}

// ---------------- launch ----------------
extern "C" void kernel_launch(void* const* d_in, const int* in_sizes, int n_in,
                              void* d_out, int out_size){
  (void)in_sizes; (void)n_in; (void)out_size;
  const float* hn  = (const float*)d_in[2];   // h_n (1,B,N,H)
  const float* ne1 = (const float*)d_in[3];
  const float* ne2 = (const float*)d_in[4];
  const float* E   = (const float*)d_in[5];
  const float* Wq  = (const float*)d_in[6];
  const float* bq  = (const float*)d_in[7];
  const float* Wk  = (const float*)d_in[8];
  const float* bk  = (const float*)d_in[9];
  const float* Wv  = (const float*)d_in[10];
  const float* bv  = (const float*)d_in[11];
  const float* taw = (const float*)d_in[12];
  const float* tab = (const float*)d_in[13];
  const float* gwp = (const float*)d_in[14];
  const float* gw  = (const float*)d_in[15];
  const float* gbp = (const float*)d_in[16];
  const float* gb  = (const float*)d_in[17];
  const float* uwp = (const float*)d_in[18];
  const float* uw  = (const float*)d_in[19];
  const float* ubp = (const float*)d_in[20];
  const float* ub  = (const float*)d_in[21];
  const float* outw= (const float*)d_in[22];
  const float* outb= (const float*)d_in[23];
  float* out = (float*)d_out;

  k_adj<<<512, 512>>>(E);
  k_prep<<<896, 64>>>(ne1, ne2, Wq, bq, Wk, bk, Wv, bv);
  k_qkvu<<<dim3(4, 512), 256>>>(hn, Wq, Wk, Wv, taw, tab);
  k_attn2<<<4096, 256>>>(taw);
  k_wgen<<<dim3(390, 12), 256>>>(ne2, gwp, gw, 24960, 0);
  k_wgen<<<dim3(195, 12), 256>>>(ne2, uwp, uw, 12480, 1);
  k_wgen<<<dim3(2, 12), 256>>>(ne2, gbp, gb, 128, 2);
  k_wgen<<<dim3(1, 12), 256>>>(ne2, ubp, ub, 64, 3);
  k_agemm<<<dim3(4, 768), 128>>>(0, 1, -1);   // y1 = A @ de
  k_agemm<<<dim3(4, 768), 128>>>(1, 2, 0);    // y2 = 2A@y1 - de
  k_comb<0><<<dim3(2, 8, 768), 256>>>();      // zr = sigmoid(...)
  k_zde<<<98304, 256>>>();                    // yz = z * de
  k_agemm<<<dim3(4, 768), 128>>>(3, 1, -1);   // y1 = A @ yz
  k_agemm<<<dim3(4, 768), 128>>>(1, 2, 3);    // y2 = 2A@y1 - yz
  k_comb<1><<<dim3(1, 8, 768), 256>>>();      // hc = tanh(...)
  k_out<<<49152, 256>>>(outw, outb, out);
}